// round 1
// baseline (speedup 1.0000x reference)
#include <cuda_runtime.h>
#include <math.h>

#define EMB 16
#define L 100
#define BATCH 8192
#define NF 4
#define FULL 0xffffffffu

// Scratch (static device allocations only — no cudaMalloc anywhere)
__device__ float g_pooled[(size_t)NF * BATCH * 6 * EMB];  // [f][row][branch][ch]
__device__ float g_stats[NF * 192];                       // per field: [sum 96][sumsq 96]
__device__ float g_A2[NF * 6 * EMB];                      // softmax(alpha)*gamma*invstd
__device__ float g_Cc[NF * EMB];                          // combined constant term

// ---------------------------------------------------------------------------
// Kernel 1: per (field,row) pooling. One warp per row. Lane = (q = lane&3
// selects float4 chunk of the 16-wide embedding, s = lane>>2 selects position
// slot; positions p = t*8+s). 8 warps/block, blockIdx.y = field.
// ---------------------------------------------------------------------------
__global__ __launch_bounds__(256) void k_pool(
    const int* __restrict__ ids_ug, const int* __restrict__ ids_urb,
    const int* __restrict__ ids_mg, const int* __restrict__ ids_mt,
    const int* __restrict__ len_ug, const int* __restrict__ len_urb,
    const int* __restrict__ len_mg, const int* __restrict__ len_mt,
    const float* __restrict__ emb_genre, const float* __restrict__ emb_movie,
    const float* __restrict__ emb_tag,
    const float* __restrict__ att_genre, const float* __restrict__ att_movie,
    const float* __restrict__ att_tag)
{
    const int f = blockIdx.y;
    const int* ids; const int* lenp; const float* tab; const float* att;
    switch (f) {
        case 0:  ids = ids_ug;  lenp = len_ug;  tab = emb_genre; att = att_genre; break;
        case 1:  ids = ids_urb; lenp = len_urb; tab = emb_movie; att = att_movie; break;
        case 2:  ids = ids_mg;  lenp = len_mg;  tab = emb_genre; att = att_genre; break;
        default: ids = ids_mt;  lenp = len_mt;  tab = emb_tag;   att = att_tag;   break;
    }

    __shared__ float ssum[96];
    __shared__ float ssq[96];
    const int tid = threadIdx.x;
    if (tid < 96) { ssum[tid] = 0.f; ssq[tid] = 0.f; }
    __syncthreads();

    const int warp = tid >> 5, lane = tid & 31;
    const int q = lane & 3, s = lane >> 2;
    const int row = blockIdx.x * 8 + warp;
    const int* idr = ids + row * L;
    const int len = lenp[row];
    const float4* tab4 = (const float4*)tab;

    float4 sum  = make_float4(0.f, 0.f, 0.f, 0.f);
    float4 sq   = make_float4(0.f, 0.f, 0.f, 0.f);
    float4 atn  = make_float4(0.f, 0.f, 0.f, 0.f);
    float den = 0.f;
    float maxv = -1.f;     int maxi = 0x7fffffff;
    float minv = 3.4e38f;  int mini = 0x7fffffff;

    for (int t = 0; t < 13; ++t) {
        const int p = t * 8 + s;
        const bool inb = (p < L);
        const bool valid = inb && (p < len);
        float4 v = make_float4(0.f, 0.f, 0.f, 0.f);
        float aw = 0.f;
        if (valid) {
            const int id = idr[p];
            v = tab4[id * 4 + q];
            aw = att[id];
        }
        float l2 = v.x * v.x + v.y * v.y + v.z * v.z + v.w * v.w;
        l2 += __shfl_xor_sync(FULL, l2, 1);
        l2 += __shfl_xor_sync(FULL, l2, 2);
        const float e = __expf(aw);   // masked p: aw=0 -> e=1 (softmax over full L, faithful)
        sum.x += v.x; sum.y += v.y; sum.z += v.z; sum.w += v.w;
        sq.x  += v.x * v.x; sq.y += v.y * v.y; sq.z += v.z * v.z; sq.w += v.w * v.w;
        atn.x += v.x * e; atn.y += v.y * e; atn.z += v.z * e; atn.w += v.w * e;
        if (inb) {
            den += e;
            if (l2 > maxv) { maxv = l2; maxi = p; }       // ascending p per lane -> first occurrence
            const float l2v = (l2 == 0.f) ? 9999.f : l2;
            if (l2v < minv) { minv = l2v; mini = p; }
        }
    }

    // Reduce across the 8 position-slots (same q class): xor 4, 8, 16.
    #pragma unroll
    for (int off = 4; off <= 16; off <<= 1) {
        sum.x += __shfl_xor_sync(FULL, sum.x, off);
        sum.y += __shfl_xor_sync(FULL, sum.y, off);
        sum.z += __shfl_xor_sync(FULL, sum.z, off);
        sum.w += __shfl_xor_sync(FULL, sum.w, off);
        sq.x  += __shfl_xor_sync(FULL, sq.x,  off);
        sq.y  += __shfl_xor_sync(FULL, sq.y,  off);
        sq.z  += __shfl_xor_sync(FULL, sq.z,  off);
        sq.w  += __shfl_xor_sync(FULL, sq.w,  off);
        atn.x += __shfl_xor_sync(FULL, atn.x, off);
        atn.y += __shfl_xor_sync(FULL, atn.y, off);
        atn.z += __shfl_xor_sync(FULL, atn.z, off);
        atn.w += __shfl_xor_sync(FULL, atn.w, off);
        den   += __shfl_xor_sync(FULL, den,   off);
        float ov = __shfl_xor_sync(FULL, maxv, off);
        int   oi = __shfl_xor_sync(FULL, maxi, off);
        if (ov > maxv || (ov == maxv && oi < maxi)) { maxv = ov; maxi = oi; }
        ov = __shfl_xor_sync(FULL, minv, off);
        oi = __shfl_xor_sync(FULL, mini, off);
        if (ov < minv || (ov == minv && oi < mini)) { minv = ov; mini = oi; }
    }

    // Branch vectors (each lane owns its 4-channel chunk; all slot groups identical)
    float4 br0 = sum;
    float4 br1 = make_float4(sum.x * 0.01f, sum.y * 0.01f, sum.z * 0.01f, sum.w * 0.01f);
    const int idm = idr[maxi];
    float4 br2 = (maxi < len) ? tab4[idm * 4 + q] : make_float4(0.f, 0.f, 0.f, 0.f);
    const int idn = idr[mini];
    float4 br3 = (mini < len) ? tab4[idn * 4 + q] : make_float4(0.f, 0.f, 0.f, 0.f);
    float4 ko;
    ko.x = 0.5f * (sum.x * sum.x - sq.x);
    ko.y = 0.5f * (sum.y * sum.y - sq.y);
    ko.z = 0.5f * (sum.z * sum.z - sq.z);
    ko.w = 0.5f * (sum.w * sum.w - sq.w);
    float n2 = ko.x * ko.x + ko.y * ko.y + ko.z * ko.z + ko.w * ko.w;
    n2 += __shfl_xor_sync(FULL, n2, 1);
    n2 += __shfl_xor_sync(FULL, n2, 2);
    const float inv = 1.f / fmaxf(sqrtf(n2), 1e-12f);
    float4 br4 = make_float4(ko.x * inv, ko.y * inv, ko.z * inv, ko.w * inv);
    const float dinv = 1.f / den;
    float4 br5 = make_float4(atn.x * dinv, atn.y * dinv, atn.z * dinv, atn.w * dinv);

    if (s == 0) {   // lanes 0..3 write their quad for all 6 branches
        float4* gp = (float4*)g_pooled;
        const size_t base = ((size_t)(f * BATCH + row) * 6) * 4 + q;
        float4 brs[6] = {br0, br1, br2, br3, br4, br5};
        #pragma unroll
        for (int b = 0; b < 6; ++b) {
            gp[base + b * 4] = brs[b];
            const int c0 = b * 16 + q * 4;
            atomicAdd(&ssum[c0 + 0], brs[b].x); atomicAdd(&ssq[c0 + 0], brs[b].x * brs[b].x);
            atomicAdd(&ssum[c0 + 1], brs[b].y); atomicAdd(&ssq[c0 + 1], brs[b].y * brs[b].y);
            atomicAdd(&ssum[c0 + 2], brs[b].z); atomicAdd(&ssq[c0 + 2], brs[b].z * brs[b].z);
            atomicAdd(&ssum[c0 + 3], brs[b].w); atomicAdd(&ssq[c0 + 3], brs[b].w * brs[b].w);
        }
    }
    __syncthreads();
    if (tid < 192) {
        const float v = (tid < 96) ? ssum[tid] : ssq[tid - 96];
        atomicAdd(&g_stats[f * 192 + tid], v);
    }
}

// ---------------------------------------------------------------------------
// Kernel 2: BN stats -> affine coefficients, folded with softmax(alpha).
// 1 block, 384 threads (t = f*96 + b*16 + c).
// ---------------------------------------------------------------------------
__global__ void k_stats(const float* __restrict__ gamma,
                        const float* __restrict__ beta,
                        const float* __restrict__ alpha)
{
    __shared__ float w[24];
    __shared__ float Carr[384];
    const int t = threadIdx.x;
    if (t < 4) {
        float a[6]; float m = -3.4e38f;
        #pragma unroll
        for (int i = 0; i < 6; ++i) { a[i] = alpha[t * 6 + i]; m = fmaxf(m, a[i]); }
        float ssum = 0.f;
        #pragma unroll
        for (int i = 0; i < 6; ++i) { a[i] = expf(a[i] - m); ssum += a[i]; }
        #pragma unroll
        for (int i = 0; i < 6; ++i) w[t * 6 + i] = a[i] / ssum;
    }
    __syncthreads();
    const int f = t / 96, r = t % 96, b = r / 16, c = r % 16;
    const float sum = g_stats[f * 192 + r];
    const float sq  = g_stats[f * 192 + 96 + r];
    const float mean = sum * (1.f / BATCH);
    const float var  = sq * (1.f / BATCH) - mean * mean;
    const float invstd = rsqrtf(var + 1e-5f);
    const float A = gamma[t] * invstd;
    const float C = beta[t] - mean * A;
    const float ww = w[f * 6 + b];
    g_A2[t] = ww * A;
    Carr[t] = ww * C;
    __syncthreads();
    if (b == 0) {
        float cc = 0.f;
        #pragma unroll
        for (int bb = 0; bb < 6; ++bb) cc += Carr[f * 96 + bb * 16 + c];
        g_Cc[f * 16 + c] = cc;
    }
}

// ---------------------------------------------------------------------------
// Kernel 3: build x[112], MLP 112->64->32->1, sigmoid. Warp per row; weights
// in smem (LDS broadcast), h1->h2 via shuffles.
// ---------------------------------------------------------------------------
__global__ __launch_bounds__(256) void k_mlp(
    const int* __restrict__ uid, const int* __restrict__ mid, const int* __restrict__ yr,
    const float* __restrict__ eu, const float* __restrict__ em, const float* __restrict__ ey,
    const float* __restrict__ W1, const float* __restrict__ b1,
    const float* __restrict__ W2, const float* __restrict__ b2,
    const float* __restrict__ W3, const float* __restrict__ b3,
    float* __restrict__ out)
{
    __shared__ float sW1[112 * 64];
    __shared__ float sW2[64 * 32];
    __shared__ float sW3[32];
    __shared__ float sb1[64];
    __shared__ float sb2[32];
    __shared__ float sb3;
    __shared__ float sx[8][112];

    const int tid = threadIdx.x;
    for (int i = tid; i < 112 * 64; i += 256) sW1[i] = W1[i];
    for (int i = tid; i < 64 * 32; i += 256) sW2[i] = W2[i];
    if (tid < 32) { sW3[tid] = W3[tid]; sb2[tid] = b2[tid]; }
    if (tid < 64) sb1[tid] = b1[tid];
    if (tid == 0) sb3 = b3[0];
    __syncthreads();

    const int warp = tid >> 5, lane = tid & 31;
    float* x = sx[warp];

    for (int row = blockIdx.x * 8 + warp; row < BATCH; row += gridDim.x * 8) {
        if (lane < 16) {
            x[lane]      = eu[(size_t)uid[row] * 16 + lane];
            x[16 + lane] = em[(size_t)mid[row] * 16 + lane];
            x[32 + lane] = ey[yr[row] * 16 + lane];
            #pragma unroll
            for (int f = 0; f < 4; ++f) {
                float acc = g_Cc[f * 16 + lane];
                const size_t base = ((size_t)(f * BATCH + row) * 6) * 16 + lane;
                #pragma unroll
                for (int b = 0; b < 6; ++b)
                    acc += g_pooled[base + b * 16] * g_A2[f * 96 + b * 16 + lane];
                x[48 + f * 16 + lane] = acc;
            }
        }
        __syncwarp();

        float h1a = sb1[lane], h1b = sb1[lane + 32];
        #pragma unroll 8
        for (int i = 0; i < 112; ++i) {
            const float xi = x[i];
            h1a += xi * sW1[i * 64 + lane];
            h1b += xi * sW1[i * 64 + lane + 32];
        }
        h1a = fmaxf(h1a, 0.f); h1b = fmaxf(h1b, 0.f);

        float h2 = sb2[lane];
        #pragma unroll
        for (int j = 0; j < 32; ++j) {
            const float v = __shfl_sync(FULL, h1a, j);
            h2 += v * sW2[j * 32 + lane];
        }
        #pragma unroll
        for (int j = 0; j < 32; ++j) {
            const float v = __shfl_sync(FULL, h1b, j);
            h2 += v * sW2[(j + 32) * 32 + lane];
        }
        h2 = fmaxf(h2, 0.f);

        float part = h2 * sW3[lane];
        #pragma unroll
        for (int off = 16; off; off >>= 1) part += __shfl_xor_sync(FULL, part, off);
        if (lane == 0) {
            const float z = part + sb3;
            out[row] = 1.f / (1.f + expf(-z));
        }
        __syncwarp();  // keep x stable until all lanes consumed it
    }
}

// ---------------------------------------------------------------------------
extern "C" void kernel_launch(void* const* d_in, const int* in_sizes, int n_in,
                              void* d_out, int out_size)
{
    (void)in_sizes; (void)n_in; (void)out_size;
    const int*   uid      = (const int*)d_in[0];
    const int*   mid      = (const int*)d_in[1];
    const int*   yr       = (const int*)d_in[2];
    const int*   ids_ug   = (const int*)d_in[3];
    const int*   ids_urb  = (const int*)d_in[4];
    const int*   ids_mg   = (const int*)d_in[5];
    const int*   ids_mt   = (const int*)d_in[6];
    const int*   len_ug   = (const int*)d_in[7];
    const int*   len_urb  = (const int*)d_in[8];
    const int*   len_mg   = (const int*)d_in[9];
    const int*   len_mt   = (const int*)d_in[10];
    const float* emb_user = (const float*)d_in[11];
    const float* emb_mov  = (const float*)d_in[12];
    const float* emb_tag  = (const float*)d_in[13];
    const float* emb_gen  = (const float*)d_in[14];
    const float* emb_year = (const float*)d_in[15];
    const float* att_mov  = (const float*)d_in[16];
    const float* att_tag  = (const float*)d_in[17];
    const float* att_gen  = (const float*)d_in[18];
    const float* bn_gamma = (const float*)d_in[19];
    const float* bn_beta  = (const float*)d_in[20];
    const float* alpha    = (const float*)d_in[21];
    const float* W1       = (const float*)d_in[22];
    const float* b1       = (const float*)d_in[23];
    const float* W2       = (const float*)d_in[24];
    const float* b2       = (const float*)d_in[25];
    const float* W3       = (const float*)d_in[26];
    const float* b3       = (const float*)d_in[27];
    float* out = (float*)d_out;

    void* statsPtr = nullptr;
    cudaGetSymbolAddress(&statsPtr, g_stats);
    cudaMemsetAsync(statsPtr, 0, sizeof(float) * NF * 192, 0);

    dim3 g1(BATCH / 8, NF);
    k_pool<<<g1, 256>>>(ids_ug, ids_urb, ids_mg, ids_mt,
                        len_ug, len_urb, len_mg, len_mt,
                        emb_gen, emb_mov, emb_tag,
                        att_gen, att_mov, att_tag);
    k_stats<<<1, 384>>>(bn_gamma, bn_beta, alpha);
    k_mlp<<<128, 256>>>(uid, mid, yr, emb_user, emb_mov, emb_year,
                        W1, b1, W2, b2, W3, b3, out);
}

// round 2
// speedup vs baseline: 1.0507x; 1.0507x over previous
#include <cuda_runtime.h>
#include <math.h>

#define EMB 16
#define L 100
#define BATCH 8192
#define NF 4
#define FULL 0xffffffffu

// Scratch (static device allocations only — no cudaMalloc anywhere)
__device__ float g_pooled[(size_t)NF * BATCH * 6 * EMB];  // [f][row][branch][ch]
__device__ float g_stats[NF * 192];                       // per field: [sum 96][sumsq 96]
__device__ float g_A2[NF * 6 * EMB];                      // softmax(alpha)*gamma*invstd
__device__ float g_Cc[NF * EMB];                          // combined constant term

// ---------------------------------------------------------------------------
// Kernel 1: per (field,row) pooling. One warp per row. lane = (q = lane&3:
// float4 chunk of the 16-wide embedding, s = lane>>2: position slot;
// positions p = t*8+s). Only valid positions (p < len) are visited; masked
// positions contribute exactly (L-len) to the softmax denominator and zeros
// elsewhere, folded in analytically.
// ---------------------------------------------------------------------------
__global__ __launch_bounds__(256) void k_pool(
    const int* __restrict__ ids_ug, const int* __restrict__ ids_urb,
    const int* __restrict__ ids_mg, const int* __restrict__ ids_mt,
    const int* __restrict__ len_ug, const int* __restrict__ len_urb,
    const int* __restrict__ len_mg, const int* __restrict__ len_mt,
    const float* __restrict__ emb_genre, const float* __restrict__ emb_movie,
    const float* __restrict__ emb_tag,
    const float* __restrict__ att_genre, const float* __restrict__ att_movie,
    const float* __restrict__ att_tag)
{
    const int f = blockIdx.y;
    const int* ids; const int* lenp; const float* tab; const float* att;
    switch (f) {
        case 0:  ids = ids_ug;  lenp = len_ug;  tab = emb_genre; att = att_genre; break;
        case 1:  ids = ids_urb; lenp = len_urb; tab = emb_movie; att = att_movie; break;
        case 2:  ids = ids_mg;  lenp = len_mg;  tab = emb_genre; att = att_genre; break;
        default: ids = ids_mt;  lenp = len_mt;  tab = emb_tag;   att = att_tag;   break;
    }

    __shared__ float ssum[96];
    __shared__ float ssq[96];
    const int tid = threadIdx.x;
    if (tid < 96) { ssum[tid] = 0.f; ssq[tid] = 0.f; }
    __syncthreads();

    const int warp = tid >> 5, lane = tid & 31;
    const int q = lane & 3, s = lane >> 2;
    const int row = blockIdx.x * 8 + warp;
    const int* idr = ids + row * L;
    const int len = lenp[row];
    const float4* tab4 = (const float4*)tab;

    float4 sum  = make_float4(0.f, 0.f, 0.f, 0.f);
    float4 sq   = make_float4(0.f, 0.f, 0.f, 0.f);
    float4 atn  = make_float4(0.f, 0.f, 0.f, 0.f);
    float den = 0.f;
    // packed argmax/argmin keys: hi32 = float bits of l2 (l2>=0 so order-
    // preserving), lo32 chosen so ties resolve to the SMALLEST p (first
    // occurrence, matching jnp.argmax/argmin).
    unsigned long long maxkey = 0ull;                    // lo = ~p  (bigger = smaller p)
    unsigned long long minkey = 0xffffffffffffffffull;   // lo =  p  (smaller = smaller p)

    const int nt = (len + 7) >> 3;
    #pragma unroll 2
    for (int t = 0; t < nt; ++t) {
        const int p = t * 8 + s;
        const bool valid = (p < len);
        float4 v = make_float4(0.f, 0.f, 0.f, 0.f);
        float aw = 0.f;
        if (valid) {
            const int id = idr[p];
            v = tab4[id * 4 + q];
            aw = att[id];
        }
        float l2 = v.x * v.x + v.y * v.y + v.z * v.z + v.w * v.w;
        l2 += __shfl_xor_sync(FULL, l2, 1);
        l2 += __shfl_xor_sync(FULL, l2, 2);
        const float e = __expf(aw);
        sum.x += v.x; sum.y += v.y; sum.z += v.z; sum.w += v.w;
        sq.x  += v.x * v.x; sq.y += v.y * v.y; sq.z += v.z * v.z; sq.w += v.w * v.w;
        atn.x += v.x * e; atn.y += v.y * e; atn.z += v.z * e; atn.w += v.w * e;
        if (valid) {
            den += e;
            const unsigned long long kmax =
                ((unsigned long long)__float_as_uint(l2) << 32) | (unsigned)(~p);
            if (kmax > maxkey) maxkey = kmax;
            const float l2v = (l2 == 0.f) ? 9999.f : l2;
            const unsigned long long kmin =
                ((unsigned long long)__float_as_uint(l2v) << 32) | (unsigned)p;
            if (kmin < minkey) minkey = kmin;
        }
    }

    // Reduce across the 8 position-slots (same q class): xor 4, 8, 16.
    #pragma unroll
    for (int off = 4; off <= 16; off <<= 1) {
        sum.x += __shfl_xor_sync(FULL, sum.x, off);
        sum.y += __shfl_xor_sync(FULL, sum.y, off);
        sum.z += __shfl_xor_sync(FULL, sum.z, off);
        sum.w += __shfl_xor_sync(FULL, sum.w, off);
        sq.x  += __shfl_xor_sync(FULL, sq.x,  off);
        sq.y  += __shfl_xor_sync(FULL, sq.y,  off);
        sq.z  += __shfl_xor_sync(FULL, sq.z,  off);
        sq.w  += __shfl_xor_sync(FULL, sq.w,  off);
        atn.x += __shfl_xor_sync(FULL, atn.x, off);
        atn.y += __shfl_xor_sync(FULL, atn.y, off);
        atn.z += __shfl_xor_sync(FULL, atn.z, off);
        atn.w += __shfl_xor_sync(FULL, atn.w, off);
        den   += __shfl_xor_sync(FULL, den,   off);
        const unsigned long long omx = __shfl_xor_sync(FULL, maxkey, off);
        if (omx > maxkey) maxkey = omx;
        const unsigned long long omn = __shfl_xor_sync(FULL, minkey, off);
        if (omn < minkey) minkey = omn;
    }
    den += (float)(L - len);                 // masked positions: e = exp(0) = 1
    const int maxi = (int)(~(unsigned)maxkey);
    const int mini = (int)(unsigned)minkey;

    // Branch vectors (each lane owns its 4-channel chunk)
    float4 br0 = sum;
    float4 br1 = make_float4(sum.x * 0.01f, sum.y * 0.01f, sum.z * 0.01f, sum.w * 0.01f);
    float4 br2 = tab4[idr[maxi] * 4 + q];    // maxi/mini always < len (len >= 1)
    float4 br3 = tab4[idr[mini] * 4 + q];
    float4 ko;
    ko.x = 0.5f * (sum.x * sum.x - sq.x);
    ko.y = 0.5f * (sum.y * sum.y - sq.y);
    ko.z = 0.5f * (sum.z * sum.z - sq.z);
    ko.w = 0.5f * (sum.w * sum.w - sq.w);
    float n2 = ko.x * ko.x + ko.y * ko.y + ko.z * ko.z + ko.w * ko.w;
    n2 += __shfl_xor_sync(FULL, n2, 1);
    n2 += __shfl_xor_sync(FULL, n2, 2);
    const float inv = 1.f / fmaxf(sqrtf(n2), 1e-12f);
    float4 br4 = make_float4(ko.x * inv, ko.y * inv, ko.z * inv, ko.w * inv);
    const float dinv = 1.f / den;
    float4 br5 = make_float4(atn.x * dinv, atn.y * dinv, atn.z * dinv, atn.w * dinv);

    if (s == 0) {   // lanes 0..3 write their quad for all 6 branches
        float4* gp = (float4*)g_pooled;
        const size_t base = ((size_t)(f * BATCH + row) * 6) * 4 + q;
        float4 brs[6] = {br0, br1, br2, br3, br4, br5};
        #pragma unroll
        for (int b = 0; b < 6; ++b) {
            gp[base + b * 4] = brs[b];
            const int c0 = b * 16 + q * 4;
            atomicAdd(&ssum[c0 + 0], brs[b].x); atomicAdd(&ssq[c0 + 0], brs[b].x * brs[b].x);
            atomicAdd(&ssum[c0 + 1], brs[b].y); atomicAdd(&ssq[c0 + 1], brs[b].y * brs[b].y);
            atomicAdd(&ssum[c0 + 2], brs[b].z); atomicAdd(&ssq[c0 + 2], brs[b].z * brs[b].z);
            atomicAdd(&ssum[c0 + 3], brs[b].w); atomicAdd(&ssq[c0 + 3], brs[b].w * brs[b].w);
        }
    }
    __syncthreads();
    if (tid < 192) {
        const float v = (tid < 96) ? ssum[tid] : ssq[tid - 96];
        atomicAdd(&g_stats[f * 192 + tid], v);
    }
}

// ---------------------------------------------------------------------------
// Kernel 2: BN stats -> affine coefficients, folded with softmax(alpha).
// 1 block, 384 threads (t = f*96 + b*16 + c).
// ---------------------------------------------------------------------------
__global__ void k_stats(const float* __restrict__ gamma,
                        const float* __restrict__ beta,
                        const float* __restrict__ alpha)
{
    __shared__ float w[24];
    __shared__ float Carr[384];
    const int t = threadIdx.x;
    if (t < 4) {
        float a[6]; float m = -3.4e38f;
        #pragma unroll
        for (int i = 0; i < 6; ++i) { a[i] = alpha[t * 6 + i]; m = fmaxf(m, a[i]); }
        float ssum = 0.f;
        #pragma unroll
        for (int i = 0; i < 6; ++i) { a[i] = expf(a[i] - m); ssum += a[i]; }
        #pragma unroll
        for (int i = 0; i < 6; ++i) w[t * 6 + i] = a[i] / ssum;
    }
    __syncthreads();
    const int f = t / 96, r = t % 96, b = r / 16, c = r % 16;
    const float sum = g_stats[f * 192 + r];
    const float sq  = g_stats[f * 192 + 96 + r];
    const float mean = sum * (1.f / BATCH);
    const float var  = sq * (1.f / BATCH) - mean * mean;
    const float invstd = rsqrtf(var + 1e-5f);
    const float A = gamma[t] * invstd;
    const float C = beta[t] - mean * A;
    const float ww = w[f * 6 + b];
    g_A2[t] = ww * A;
    Carr[t] = ww * C;
    __syncthreads();
    if (b == 0) {
        float cc = 0.f;
        #pragma unroll
        for (int bb = 0; bb < 6; ++bb) cc += Carr[f * 96 + bb * 16 + c];
        g_Cc[f * 16 + c] = cc;
    }
}

// ---------------------------------------------------------------------------
// Kernel 3: build x[112], MLP 112->64->32->1, sigmoid. Warp per row; weights
// in smem (LDS broadcast), h1->h2 via shuffles. x-build split across both
// half-warps.
// ---------------------------------------------------------------------------
__global__ __launch_bounds__(256) void k_mlp(
    const int* __restrict__ uid, const int* __restrict__ mid, const int* __restrict__ yr,
    const float* __restrict__ eu, const float* __restrict__ em, const float* __restrict__ ey,
    const float* __restrict__ W1, const float* __restrict__ b1,
    const float* __restrict__ W2, const float* __restrict__ b2,
    const float* __restrict__ W3, const float* __restrict__ b3,
    float* __restrict__ out)
{
    __shared__ float sW1[112 * 64];
    __shared__ float sW2[64 * 32];
    __shared__ float sW3[32];
    __shared__ float sb1[64];
    __shared__ float sb2[32];
    __shared__ float sb3;
    __shared__ float sx[8][112];

    const int tid = threadIdx.x;
    for (int i = tid; i < 112 * 64; i += 256) sW1[i] = W1[i];
    for (int i = tid; i < 64 * 32; i += 256) sW2[i] = W2[i];
    if (tid < 32) { sW3[tid] = W3[tid]; sb2[tid] = b2[tid]; }
    if (tid < 64) sb1[tid] = b1[tid];
    if (tid == 0) sb3 = b3[0];
    __syncthreads();

    const int warp = tid >> 5, lane = tid & 31;
    float* x = sx[warp];

    for (int row = blockIdx.x * 8 + warp; row < BATCH; row += gridDim.x * 8) {
        {
            const int c = lane & 15;
            const int half = lane >> 4;            // 0: emb1 + fields 0,1;  1: fields 2,3
            if (half == 0) {
                x[c]      = eu[(size_t)uid[row] * 16 + c];
                x[16 + c] = em[(size_t)mid[row] * 16 + c];
                x[32 + c] = ey[yr[row] * 16 + c];
            }
            #pragma unroll
            for (int k = 0; k < 2; ++k) {
                const int f = half * 2 + k;
                float acc = g_Cc[f * 16 + c];
                const size_t base = ((size_t)(f * BATCH + row) * 6) * 16 + c;
                #pragma unroll
                for (int b = 0; b < 6; ++b)
                    acc += g_pooled[base + b * 16] * g_A2[f * 96 + b * 16 + c];
                x[48 + f * 16 + c] = acc;
            }
        }
        __syncwarp();

        float h1a = sb1[lane], h1b = sb1[lane + 32];
        #pragma unroll 8
        for (int i = 0; i < 112; ++i) {
            const float xi = x[i];
            h1a += xi * sW1[i * 64 + lane];
            h1b += xi * sW1[i * 64 + lane + 32];
        }
        h1a = fmaxf(h1a, 0.f); h1b = fmaxf(h1b, 0.f);

        float h2 = sb2[lane];
        #pragma unroll
        for (int j = 0; j < 32; ++j) {
            const float v = __shfl_sync(FULL, h1a, j);
            h2 += v * sW2[j * 32 + lane];
        }
        #pragma unroll
        for (int j = 0; j < 32; ++j) {
            const float v = __shfl_sync(FULL, h1b, j);
            h2 += v * sW2[(j + 32) * 32 + lane];
        }
        h2 = fmaxf(h2, 0.f);

        float part = h2 * sW3[lane];
        #pragma unroll
        for (int off = 16; off; off >>= 1) part += __shfl_xor_sync(FULL, part, off);
        if (lane == 0) {
            const float z = part + sb3;
            out[row] = 1.f / (1.f + expf(-z));
        }
        __syncwarp();  // keep x stable until all lanes consumed it
    }
}

// ---------------------------------------------------------------------------
extern "C" void kernel_launch(void* const* d_in, const int* in_sizes, int n_in,
                              void* d_out, int out_size)
{
    (void)in_sizes; (void)n_in; (void)out_size;
    const int*   uid      = (const int*)d_in[0];
    const int*   mid      = (const int*)d_in[1];
    const int*   yr       = (const int*)d_in[2];
    const int*   ids_ug   = (const int*)d_in[3];
    const int*   ids_urb  = (const int*)d_in[4];
    const int*   ids_mg   = (const int*)d_in[5];
    const int*   ids_mt   = (const int*)d_in[6];
    const int*   len_ug   = (const int*)d_in[7];
    const int*   len_urb  = (const int*)d_in[8];
    const int*   len_mg   = (const int*)d_in[9];
    const int*   len_mt   = (const int*)d_in[10];
    const float* emb_user = (const float*)d_in[11];
    const float* emb_mov  = (const float*)d_in[12];
    const float* emb_tag  = (const float*)d_in[13];
    const float* emb_gen  = (const float*)d_in[14];
    const float* emb_year = (const float*)d_in[15];
    const float* att_mov  = (const float*)d_in[16];
    const float* att_tag  = (const float*)d_in[17];
    const float* att_gen  = (const float*)d_in[18];
    const float* bn_gamma = (const float*)d_in[19];
    const float* bn_beta  = (const float*)d_in[20];
    const float* alpha    = (const float*)d_in[21];
    const float* W1       = (const float*)d_in[22];
    const float* b1       = (const float*)d_in[23];
    const float* W2       = (const float*)d_in[24];
    const float* b2       = (const float*)d_in[25];
    const float* W3       = (const float*)d_in[26];
    const float* b3       = (const float*)d_in[27];
    float* out = (float*)d_out;

    void* statsPtr = nullptr;
    cudaGetSymbolAddress(&statsPtr, g_stats);
    cudaMemsetAsync(statsPtr, 0, sizeof(float) * NF * 192, 0);

    dim3 g1(BATCH / 8, NF);
    k_pool<<<g1, 256>>>(ids_ug, ids_urb, ids_mg, ids_mt,
                        len_ug, len_urb, len_mg, len_mt,
                        emb_gen, emb_mov, emb_tag,
                        att_gen, att_mov, att_tag);
    k_stats<<<1, 384>>>(bn_gamma, bn_beta, alpha);
    k_mlp<<<256, 256>>>(uid, mid, yr, emb_user, emb_mov, emb_year,
                        W1, b1, W2, b2, W3, b3, out);
}

// round 3
// speedup vs baseline: 1.1556x; 1.0998x over previous
#include <cuda_runtime.h>
#include <math.h>

#define EMB 16
#define L 100
#define BATCH 8192
#define NF 4
#define FULL 0xffffffffu

// Scratch (static device allocations only — no cudaMalloc anywhere)
__device__ float g_pooled[(size_t)NF * BATCH * 6 * EMB];  // [f][row][branch][ch]
__device__ float g_stats[NF * 192];                       // per field: [sum 96][sumsq 96] (zeroed by k_stats each run)
__device__ float g_A2[NF * 6 * EMB];                      // softmax(alpha)*gamma*invstd
__device__ float g_Cc[NF * EMB];                          // combined constant term

// ---------------------------------------------------------------------------
// Kernel 1: per (field,row) pooling. One warp per row. lane = (q = lane&3:
// float4 chunk of the 16-wide embedding, s = lane>>2: position slot;
// positions p = t*8+s). ids staged in smem (coalesced) so the gather chain is
// LDS->LDG instead of LDG->LDG; position loop fully unrolled + predicated so
// gathers batch for high MLP. Masked positions contribute exactly (L-len) to
// the softmax denominator and zeros elsewhere, folded analytically.
// ---------------------------------------------------------------------------
__global__ __launch_bounds__(256, 6) void k_pool(
    const int* __restrict__ ids_ug, const int* __restrict__ ids_urb,
    const int* __restrict__ ids_mg, const int* __restrict__ ids_mt,
    const int* __restrict__ len_ug, const int* __restrict__ len_urb,
    const int* __restrict__ len_mg, const int* __restrict__ len_mt,
    const float* __restrict__ emb_genre, const float* __restrict__ emb_movie,
    const float* __restrict__ emb_tag,
    const float* __restrict__ att_genre, const float* __restrict__ att_movie,
    const float* __restrict__ att_tag)
{
    const int f = blockIdx.y;
    const int* ids; const int* lenp; const float* tab; const float* att;
    switch (f) {
        case 0:  ids = ids_ug;  lenp = len_ug;  tab = emb_genre; att = att_genre; break;
        case 1:  ids = ids_urb; lenp = len_urb; tab = emb_movie; att = att_movie; break;
        case 2:  ids = ids_mg;  lenp = len_mg;  tab = emb_genre; att = att_genre; break;
        default: ids = ids_mt;  lenp = len_mt;  tab = emb_tag;   att = att_tag;   break;
    }

    __shared__ int sids[8][100];
    __shared__ float ssum[96];
    __shared__ float ssq[96];
    const int tid = threadIdx.x;
    if (tid < 96) { ssum[tid] = 0.f; ssq[tid] = 0.f; }
    __syncthreads();

    const int warp = tid >> 5, lane = tid & 31;
    const int q = lane & 3, s = lane >> 2;
    const int row = blockIdx.x * 8 + warp;
    const int len = lenp[row];
    const float4* tab4 = (const float4*)tab;

    // Stage the 100 ids coalesced: 25 int4s (row*400 bytes is 16B-aligned).
    {
        const int4* idr4 = (const int4*)(ids + row * L);
        if (lane < 25) ((int4*)sids[warp])[lane] = idr4[lane];
    }
    __syncwarp();
    const int* idr = sids[warp];

    float4 sum  = make_float4(0.f, 0.f, 0.f, 0.f);
    float4 sq   = make_float4(0.f, 0.f, 0.f, 0.f);
    float4 atn  = make_float4(0.f, 0.f, 0.f, 0.f);
    float den = 0.f;
    // packed argmax/argmin keys: hi32 = float bits of l2 (l2>=0, order-
    // preserving), lo32 chosen so ties resolve to the SMALLEST p (first
    // occurrence, matching jnp.argmax/argmin).
    unsigned long long maxkey = 0ull;                    // lo = ~p
    unsigned long long minkey = 0xffffffffffffffffull;   // lo =  p

    #pragma unroll
    for (int t = 0; t < 13; ++t) {
        const int p = t * 8 + s;
        const bool valid = (p < len);                    // len <= 100, so p < L too
        float4 v = make_float4(0.f, 0.f, 0.f, 0.f);
        float aw = 0.f;
        if (valid) {
            const int id = idr[p];
            v = tab4[id * 4 + q];
            aw = att[id];
        }
        float l2 = v.x * v.x + v.y * v.y + v.z * v.z + v.w * v.w;
        l2 += __shfl_xor_sync(FULL, l2, 1);
        l2 += __shfl_xor_sync(FULL, l2, 2);
        const float e = __expf(aw);
        sum.x += v.x; sum.y += v.y; sum.z += v.z; sum.w += v.w;
        sq.x  += v.x * v.x; sq.y += v.y * v.y; sq.z += v.z * v.z; sq.w += v.w * v.w;
        atn.x += v.x * e; atn.y += v.y * e; atn.z += v.z * e; atn.w += v.w * e;
        if (valid) {
            den += e;
            const unsigned long long kmax =
                ((unsigned long long)__float_as_uint(l2) << 32) | (unsigned)(~p);
            if (kmax > maxkey) maxkey = kmax;
            const float l2v = (l2 == 0.f) ? 9999.f : l2;
            const unsigned long long kmin =
                ((unsigned long long)__float_as_uint(l2v) << 32) | (unsigned)p;
            if (kmin < minkey) minkey = kmin;
        }
    }

    // Reduce across the 8 position-slots (same q class): xor 4, 8, 16.
    #pragma unroll
    for (int off = 4; off <= 16; off <<= 1) {
        sum.x += __shfl_xor_sync(FULL, sum.x, off);
        sum.y += __shfl_xor_sync(FULL, sum.y, off);
        sum.z += __shfl_xor_sync(FULL, sum.z, off);
        sum.w += __shfl_xor_sync(FULL, sum.w, off);
        sq.x  += __shfl_xor_sync(FULL, sq.x,  off);
        sq.y  += __shfl_xor_sync(FULL, sq.y,  off);
        sq.z  += __shfl_xor_sync(FULL, sq.z,  off);
        sq.w  += __shfl_xor_sync(FULL, sq.w,  off);
        atn.x += __shfl_xor_sync(FULL, atn.x, off);
        atn.y += __shfl_xor_sync(FULL, atn.y, off);
        atn.z += __shfl_xor_sync(FULL, atn.z, off);
        atn.w += __shfl_xor_sync(FULL, atn.w, off);
        den   += __shfl_xor_sync(FULL, den,   off);
        const unsigned long long omx = __shfl_xor_sync(FULL, maxkey, off);
        if (omx > maxkey) maxkey = omx;
        const unsigned long long omn = __shfl_xor_sync(FULL, minkey, off);
        if (omn < minkey) minkey = omn;
    }
    den += (float)(L - len);                 // masked positions: e = exp(0) = 1
    const int maxi = (int)(~(unsigned)maxkey);
    const int mini = (int)(unsigned)minkey;

    // Branch vectors (each lane owns its 4-channel chunk)
    float4 br0 = sum;
    float4 br1 = make_float4(sum.x * 0.01f, sum.y * 0.01f, sum.z * 0.01f, sum.w * 0.01f);
    float4 br2 = tab4[idr[maxi] * 4 + q];    // maxi/mini always valid (len >= 1)
    float4 br3 = tab4[idr[mini] * 4 + q];
    float4 ko;
    ko.x = 0.5f * (sum.x * sum.x - sq.x);
    ko.y = 0.5f * (sum.y * sum.y - sq.y);
    ko.z = 0.5f * (sum.z * sum.z - sq.z);
    ko.w = 0.5f * (sum.w * sum.w - sq.w);
    float n2 = ko.x * ko.x + ko.y * ko.y + ko.z * ko.z + ko.w * ko.w;
    n2 += __shfl_xor_sync(FULL, n2, 1);
    n2 += __shfl_xor_sync(FULL, n2, 2);
    const float inv = 1.f / fmaxf(sqrtf(n2), 1e-12f);
    float4 br4 = make_float4(ko.x * inv, ko.y * inv, ko.z * inv, ko.w * inv);
    const float dinv = 1.f / den;
    float4 br5 = make_float4(atn.x * dinv, atn.y * dinv, atn.z * dinv, atn.w * dinv);

    if (s == 0) {   // lanes 0..3 write their quad for all 6 branches
        float4* gp = (float4*)g_pooled;
        const size_t base = ((size_t)(f * BATCH + row) * 6) * 4 + q;
        float4 brs[6] = {br0, br1, br2, br3, br4, br5};
        #pragma unroll
        for (int b = 0; b < 6; ++b) {
            gp[base + b * 4] = brs[b];
            const int c0 = b * 16 + q * 4;
            atomicAdd(&ssum[c0 + 0], brs[b].x); atomicAdd(&ssq[c0 + 0], brs[b].x * brs[b].x);
            atomicAdd(&ssum[c0 + 1], brs[b].y); atomicAdd(&ssq[c0 + 1], brs[b].y * brs[b].y);
            atomicAdd(&ssum[c0 + 2], brs[b].z); atomicAdd(&ssq[c0 + 2], brs[b].z * brs[b].z);
            atomicAdd(&ssum[c0 + 3], brs[b].w); atomicAdd(&ssq[c0 + 3], brs[b].w * brs[b].w);
        }
    }
    __syncthreads();
    if (tid < 192) {
        const float v = (tid < 96) ? ssum[tid] : ssq[tid - 96];
        atomicAdd(&g_stats[f * 192 + tid], v);
    }
}

// ---------------------------------------------------------------------------
// Kernel 2: BN stats -> affine coefficients, folded with softmax(alpha).
// 1 block, 384 threads (t = f*96 + b*16 + c). Also re-zeroes g_stats so the
// next graph replay starts clean (replaces the memset launch).
// ---------------------------------------------------------------------------
__global__ void k_stats(const float* __restrict__ gamma,
                        const float* __restrict__ beta,
                        const float* __restrict__ alpha)
{
    __shared__ float w[24];
    __shared__ float Carr[384];
    const int t = threadIdx.x;
    if (t < 4) {
        float a[6]; float m = -3.4e38f;
        #pragma unroll
        for (int i = 0; i < 6; ++i) { a[i] = alpha[t * 6 + i]; m = fmaxf(m, a[i]); }
        float ssum = 0.f;
        #pragma unroll
        for (int i = 0; i < 6; ++i) { a[i] = expf(a[i] - m); ssum += a[i]; }
        #pragma unroll
        for (int i = 0; i < 6; ++i) w[t * 6 + i] = a[i] / ssum;
    }
    __syncthreads();
    const int f = t / 96, r = t % 96, b = r / 16, c = r % 16;
    const float sum = g_stats[f * 192 + r];
    const float sq  = g_stats[f * 192 + 96 + r];
    g_stats[f * 192 + r] = 0.f;              // reset for next replay
    g_stats[f * 192 + 96 + r] = 0.f;
    const float mean = sum * (1.f / BATCH);
    const float var  = sq * (1.f / BATCH) - mean * mean;
    const float invstd = rsqrtf(var + 1e-5f);
    const float A = gamma[t] * invstd;
    const float C = beta[t] - mean * A;
    const float ww = w[f * 6 + b];
    g_A2[t] = ww * A;
    Carr[t] = ww * C;
    __syncthreads();
    if (b == 0) {
        float cc = 0.f;
        #pragma unroll
        for (int bb = 0; bb < 6; ++bb) cc += Carr[f * 96 + bb * 16 + c];
        g_Cc[f * 16 + c] = cc;
    }
}

// ---------------------------------------------------------------------------
// Kernel 3: build x[112], MLP 112->64->32->1, sigmoid. Warp per row; weights
// in smem (LDS broadcast), h1->h2 via shuffles. x-build split across both
// half-warps.
// ---------------------------------------------------------------------------
__global__ __launch_bounds__(256) void k_mlp(
    const int* __restrict__ uid, const int* __restrict__ mid, const int* __restrict__ yr,
    const float* __restrict__ eu, const float* __restrict__ em, const float* __restrict__ ey,
    const float* __restrict__ W1, const float* __restrict__ b1,
    const float* __restrict__ W2, const float* __restrict__ b2,
    const float* __restrict__ W3, const float* __restrict__ b3,
    float* __restrict__ out)
{
    __shared__ float sW1[112 * 64];
    __shared__ float sW2[64 * 32];
    __shared__ float sW3[32];
    __shared__ float sb1[64];
    __shared__ float sb2[32];
    __shared__ float sb3;
    __shared__ float sx[8][112];

    const int tid = threadIdx.x;
    for (int i = tid; i < 112 * 64; i += 256) sW1[i] = W1[i];
    for (int i = tid; i < 64 * 32; i += 256) sW2[i] = W2[i];
    if (tid < 32) { sW3[tid] = W3[tid]; sb2[tid] = b2[tid]; }
    if (tid < 64) sb1[tid] = b1[tid];
    if (tid == 0) sb3 = b3[0];
    __syncthreads();

    const int warp = tid >> 5, lane = tid & 31;
    float* x = sx[warp];

    for (int row = blockIdx.x * 8 + warp; row < BATCH; row += gridDim.x * 8) {
        {
            const int c = lane & 15;
            const int half = lane >> 4;            // 0: emb1 + fields 0,1;  1: fields 2,3
            if (half == 0) {
                x[c]      = eu[(size_t)uid[row] * 16 + c];
                x[16 + c] = em[(size_t)mid[row] * 16 + c];
                x[32 + c] = ey[yr[row] * 16 + c];
            }
            #pragma unroll
            for (int k = 0; k < 2; ++k) {
                const int f = half * 2 + k;
                float acc = g_Cc[f * 16 + c];
                const size_t base = ((size_t)(f * BATCH + row) * 6) * 16 + c;
                #pragma unroll
                for (int b = 0; b < 6; ++b)
                    acc += g_pooled[base + b * 16] * g_A2[f * 96 + b * 16 + c];
                x[48 + f * 16 + c] = acc;
            }
        }
        __syncwarp();

        float h1a = sb1[lane], h1b = sb1[lane + 32];
        #pragma unroll 8
        for (int i = 0; i < 112; ++i) {
            const float xi = x[i];
            h1a += xi * sW1[i * 64 + lane];
            h1b += xi * sW1[i * 64 + lane + 32];
        }
        h1a = fmaxf(h1a, 0.f); h1b = fmaxf(h1b, 0.f);

        float h2 = sb2[lane];
        #pragma unroll
        for (int j = 0; j < 32; ++j) {
            const float v = __shfl_sync(FULL, h1a, j);
            h2 += v * sW2[j * 32 + lane];
        }
        #pragma unroll
        for (int j = 0; j < 32; ++j) {
            const float v = __shfl_sync(FULL, h1b, j);
            h2 += v * sW2[(j + 32) * 32 + lane];
        }
        h2 = fmaxf(h2, 0.f);

        float part = h2 * sW3[lane];
        #pragma unroll
        for (int off = 16; off; off >>= 1) part += __shfl_xor_sync(FULL, part, off);
        if (lane == 0) {
            const float z = part + sb3;
            out[row] = 1.f / (1.f + expf(-z));
        }
        __syncwarp();  // keep x stable until all lanes consumed it
    }
}

// ---------------------------------------------------------------------------
extern "C" void kernel_launch(void* const* d_in, const int* in_sizes, int n_in,
                              void* d_out, int out_size)
{
    (void)in_sizes; (void)n_in; (void)out_size;
    const int*   uid      = (const int*)d_in[0];
    const int*   mid      = (const int*)d_in[1];
    const int*   yr       = (const int*)d_in[2];
    const int*   ids_ug   = (const int*)d_in[3];
    const int*   ids_urb  = (const int*)d_in[4];
    const int*   ids_mg   = (const int*)d_in[5];
    const int*   ids_mt   = (const int*)d_in[6];
    const int*   len_ug   = (const int*)d_in[7];
    const int*   len_urb  = (const int*)d_in[8];
    const int*   len_mg   = (const int*)d_in[9];
    const int*   len_mt   = (const int*)d_in[10];
    const float* emb_user = (const float*)d_in[11];
    const float* emb_mov  = (const float*)d_in[12];
    const float* emb_tag  = (const float*)d_in[13];
    const float* emb_gen  = (const float*)d_in[14];
    const float* emb_year = (const float*)d_in[15];
    const float* att_mov  = (const float*)d_in[16];
    const float* att_tag  = (const float*)d_in[17];
    const float* att_gen  = (const float*)d_in[18];
    const float* bn_gamma = (const float*)d_in[19];
    const float* bn_beta  = (const float*)d_in[20];
    const float* alpha    = (const float*)d_in[21];
    const float* W1       = (const float*)d_in[22];
    const float* b1       = (const float*)d_in[23];
    const float* W2       = (const float*)d_in[24];
    const float* b2       = (const float*)d_in[25];
    const float* W3       = (const float*)d_in[26];
    const float* b3       = (const float*)d_in[27];
    float* out = (float*)d_out;

    dim3 g1(BATCH / 8, NF);
    k_pool<<<g1, 256>>>(ids_ug, ids_urb, ids_mg, ids_mt,
                        len_ug, len_urb, len_mg, len_mt,
                        emb_gen, emb_mov, emb_tag,
                        att_gen, att_mov, att_tag);
    k_stats<<<1, 384>>>(bn_gamma, bn_beta, alpha);
    k_mlp<<<256, 256>>>(uid, mid, yr, emb_user, emb_mov, emb_year,
                        W1, b1, W2, b2, W3, b3, out);
}